// round 11
// baseline (speedup 1.0000x reference)
#include <cuda_runtime.h>
#include <cuda_fp16.h>
#include <cstdint>

#define N_OUT_C 50000
#define KNN 32
#define CIN 16
#define COUT 32
#define KC 1024
#define MTILE2 64
#define NTILES2 784             // 784*64 = 50176 >= 50000
#define NGROUPS1 6250           // 50000/8, groups of 8 outputs

// ============== device scratch (static, zero-init, no allocations) ==========
__device__ __half g_B16[(size_t)50176 * KC];      // 102.8 MB row-major fp16
__device__ uint4  g_Wfrag[64 * 4 * 32];           // [k16][nb][lane] = b0h,b1h,b0l,b1l
__device__ float  g_den[N_OUT_C];

__device__ __forceinline__ uint32_t smem_u32(const void* p) {
    uint32_t a;
    asm("{ .reg .u64 t; cvta.to.shared.u64 t, %1; cvt.u32.u64 %0, t; }"
        : "=r"(a) : "l"(p));
    return a;
}
__device__ __forceinline__ uint32_t packh2(__half a, __half b) {
    __half2 h = __halves2half2(a, b);
    return *reinterpret_cast<uint32_t*>(&h);
}
__device__ __forceinline__ void ldsm_x4(uint32_t* a, uint32_t addr) {
    asm volatile("ldmatrix.sync.aligned.m8n8.x4.shared.b16 {%0,%1,%2,%3}, [%4];"
                 : "=r"(a[0]), "=r"(a[1]), "=r"(a[2]), "=r"(a[3]) : "r"(addr));
}
__device__ __forceinline__ void mma16816(float* d, const uint32_t* a,
                                         uint32_t b0, uint32_t b1) {
    asm volatile("mma.sync.aligned.m16n8k16.row.col.f32.f16.f16.f32 "
                 "{%0,%1,%2,%3}, {%4,%5,%6,%7}, {%8,%9}, {%0,%1,%2,%3};"
                 : "+f"(d[0]), "+f"(d[1]), "+f"(d[2]), "+f"(d[3])
                 : "r"(a[0]), "r"(a[1]), "r"(a[2]), "r"(a[3]), "r"(b0), "r"(b1));
}
__device__ __forceinline__ void cp16(uint32_t dst, const void* src) {
    asm volatile("cp.async.ca.shared.global [%0], [%1], 16;"
                 :: "r"(dst), "l"(src) : "memory");
}

// ====== K0: pre-pack W into per-lane mma B-fragments (hi/lo planes) ========
__global__ void k0_wfrag(const float* __restrict__ kernW) {
    int i = blockIdx.x * 256 + threadIdx.x;       // 8192 total
    if (i >= 64 * 4 * 32) return;
    int k16 = i >> 7, r = i & 127, nb = r >> 5, lane = r & 31;
    int t = lane & 3, g = lane >> 2, n = nb * 8 + g;
    int kb = k16 * 16 + 2 * t;
    float w00 = kernW[(kb + 0) * COUT + n];
    float w01 = kernW[(kb + 1) * COUT + n];
    float w10 = kernW[(kb + 8) * COUT + n];
    float w11 = kernW[(kb + 9) * COUT + n];
    __half h00 = __float2half_rn(w00), h01 = __float2half_rn(w01);
    __half h10 = __float2half_rn(w10), h11 = __float2half_rn(w11);
    __half l00 = __float2half_rn(w00 - __half2float(h00));
    __half l01 = __float2half_rn(w01 - __half2float(h01));
    __half l10 = __float2half_rn(w10 - __half2float(h10));
    __half l11 = __float2half_rn(w11 - __half2float(h11));
    uint4 v;
    v.x = packh2(h00, h01);   // b0 hi
    v.y = packh2(h10, h11);   // b1 hi
    v.z = packh2(l00, l01);   // b0 lo
    v.w = packh2(l10, l11);   // b1 lo
    g_Wfrag[i] = v;
}

// ========== Fused K1+K2: CTA owns one 64-row tile end-to-end ==========
#define NW1 4

struct __align__(16) Smem1 {
    float  B[NW1][KC * 2];        // 32768 B, pair-interleaved [kc][2 outs]
    float4 meta4[NW1][2][KNN];    // 4096 B
    int    packs[NW1][2][KNN];    // 1024 B
};                                // 37888 B -> up to 6 CTAs/SM

#define K2_A_STAGE (MTILE2 * 144)   // 9216 B; aliases the front of Smem1

__global__ __launch_bounds__(128, 6)
void k12_fused(const float* __restrict__ feats,
               const float* __restrict__ inp_points,
               const float* __restrict__ out_points,
               const float* __restrict__ out_extents,
               const float* __restrict__ scale_compat,
               const int*   __restrict__ nidx,
               const float* __restrict__ ndist,
               const float* __restrict__ bias,
               float* __restrict__ out)
{
    extern __shared__ unsigned char raw1[];
    Smem1* S = reinterpret_cast<Smem1*>(raw1);
    const int tid = threadIdx.x, wid = tid >> 5, lane = tid & 31;
    const int tile = blockIdx.x;

    // ================= Phase 1: scatter the tile's 8 groups =================
    for (int j = 0; j < 8; j++) {
        const int g = tile * 8 + j;
        if (g >= NGROUPS1) break;          // tail groups: rows stay zero
        const int obase = g * 8 + wid * 2;

        {   // zero B
            float4* Bz = reinterpret_cast<float4*>(S->B[wid]);
            #pragma unroll
            for (int z = 0; z < 16; z++)
                Bz[z * 32 + lane] = make_float4(0.f, 0.f, 0.f, 0.f);
        }

        #pragma unroll
        for (int s = 0; s < 2; s++) {   // geometry, lane = edge
            const int o = obase + s;
            const int eid = o * KNN + lane;
            const int nbr = nidx[eid];
            const float dist = ndist[eid];
            const float sc = scale_compat[eid];
            float tt = 1.f - dist * dist;
            float win = fminf(fmaxf(tt * tt * tt, 0.f), 1.f);
            const float imp = sc * win;

            const float pix = inp_points[nbr * 3 + 0];
            const float piy = inp_points[nbr * 3 + 1];
            const float piz = inp_points[nbr * 3 + 2];
            const float inv = __fdividef(2.f, out_extents[o]);
            const float rx = (pix - out_points[o * 3 + 0]) * inv;
            const float ry = (piy - out_points[o * 3 + 1]) * inv;
            const float rz = (piz - out_points[o * 3 + 2]) * inv;

            const float r = sqrtf(rx * rx + ry * ry + rz * rz);
            const float linf = fmaxf(fabsf(rx), fmaxf(fabsf(ry), fabsf(rz)));
            const float sf = __fdividef(r, fmaxf(linf, 1e-12f));
            float tx = fminf(fmaxf((rx * sf * 0.5f + 0.5f) * 3.f, 0.f), 3.f);
            float ty = fminf(fmaxf((ry * sf * 0.5f + 0.5f) * 3.f, 0.f), 3.f);
            float tz = fminf(fmaxf((rz * sf * 0.5f + 0.5f) * 3.f, 0.f), 3.f);
            float t0x = fminf(floorf(tx), 2.f);
            float t0y = fminf(floorf(ty), 2.f);
            float t0z = fminf(floorf(tz), 2.f);
            int ix = (int)t0x, iy = (int)t0y, iz = (int)t0z;

            S->meta4[wid][s][lane] = make_float4(tx - t0x, ty - t0y, tz - t0z, imp);
            S->packs[wid][s][lane] = nbr | (ix << 20) | (iy << 22) | (iz << 24);

            float dsum = imp;
            #pragma unroll
            for (int off = 16; off; off >>= 1)
                dsum += __shfl_xor_sync(0xffffffffu, dsum, off);
            if (lane == 0) g_den[o] = dsum;
        }
        __syncwarp();

        {   // scatter: half-warp h -> slot h, bank (2c+h)%32 conflict-free
            const int h = lane >> 4, c = lane & 15;
            float* Bw = S->B[wid];
            const float4* m4 = S->meta4[wid][h];
            const int* pk = S->packs[wid][h];
            #pragma unroll 4
            for (int e = 0; e < KNN; e++) {
                const float4 m = m4[e];
                const int p = pk[e];
                const int nb = p & 0xFFFFF;
                const int ix = (p >> 20) & 3, iy = (p >> 22) & 3, iz = (p >> 24) & 3;
                const float fe = __ldg(&feats[nb * CIN + c]) * m.w;
                const float ax1 = fe * m.x, ax0 = fe - ax1;
                const float v01 = ax0 * m.y, v00 = ax0 - v01;
                const float v11 = ax1 * m.y, v10 = ax1 - v11;
                const float wz1 = m.z, wz0 = 1.f - m.z;
                float* Bp = Bw + ((ix * 16 + iy * 4 + iz) * 32 + c * 2 + h);
                Bp[0]   += v00 * wz0;  Bp[32]  += v00 * wz1;
                Bp[128] += v01 * wz0;  Bp[160] += v01 * wz1;
                Bp[512] += v10 * wz0;  Bp[544] += v10 * wz1;
                Bp[640] += v11 * wz0;  Bp[672] += v11 * wz1;
            }
        }
        __syncwarp();

        {   // writeout: row-major fp16, coalesced
            __half2* d0 = reinterpret_cast<__half2*>(g_B16 + (size_t)obase * KC);
            __half2* d1 = reinterpret_cast<__half2*>(g_B16 + (size_t)(obase + 1) * KC);
            const float4* Bq = reinterpret_cast<const float4*>(S->B[wid]);
            #pragma unroll 4
            for (int kt = 0; kt < 16; kt++) {
                float4 v = Bq[kt * 32 + lane];  // (kc,h0)(kc,h1)(kc+1,h0)(kc+1,h1)
                d0[kt * 32 + lane] = __floats2half2_rn(v.x, v.z);
                d1[kt * 32 + lane] = __floats2half2_rn(v.y, v.w);
            }
        }
        __syncwarp();
    }

    // __syncthreads orders this CTA's STG writes before its own cp.async reads
    __syncthreads();

    // ================= Phase 2: GEMM this CTA's 64-row tile =================
    {
        const uint32_t sA = smem_u32(raw1);            // alias front of Smem1
        const int w = wid;
        const int g2 = lane >> 2, t2 = lane & 3;
        const size_t abase = (size_t)tile * MTILE2 * KC;   // halfs

        #pragma unroll
        for (int q = 0; q < 4; q++) {
            int idx = tid + q * 128;               // 0..511
            int row = idx >> 3, j = idx & 7;
            cp16(sA + row * 144 + j * 16,
                 g_B16 + abase + (size_t)row * KC + j * 8);
        }
        asm volatile("cp.async.commit_group;" ::: "memory");

        float acc[4][4];
        #pragma unroll
        for (int nb = 0; nb < 4; nb++)
            #pragma unroll
            for (int i = 0; i < 4; i++) acc[nb][i] = 0.f;

        const uint32_t aBase = sA + (w * 16 + (lane & 15)) * 144 + (lane >> 4) * 16;

        for (int c = 0; c < 16; c++) {
            if (c < 15) {
                #pragma unroll
                for (int q = 0; q < 4; q++) {
                    int idx = tid + q * 128;
                    int row = idx >> 3, j = idx & 7;
                    cp16(sA + ((c + 1) & 1) * K2_A_STAGE + row * 144 + j * 16,
                         g_B16 + abase + (size_t)row * KC + (c + 1) * 64 + j * 8);
                }
                asm volatile("cp.async.commit_group;" ::: "memory");
                asm volatile("cp.async.wait_group 1;" ::: "memory");
            } else {
                asm volatile("cp.async.wait_group 0;" ::: "memory");
            }
            __syncthreads();

            const uint32_t aStage = aBase + (c & 1) * K2_A_STAGE;
            #pragma unroll
            for (int kbl = 0; kbl < 4; kbl++) {
                uint32_t a[4];
                ldsm_x4(a, aStage + kbl * 32);
                const uint4* wf = g_Wfrag + (c * 4 + kbl) * 128 + lane;
                #pragma unroll
                for (int nb = 0; nb < 4; nb++) {
                    const uint4 wv = __ldg(&wf[nb * 32]);
                    mma16816(acc[nb], a, wv.x, wv.y);   // hi plane
                    mma16816(acc[nb], a, wv.z, wv.w);   // lo plane
                }
            }
            __syncthreads();
        }

        // epilogue: normalize, bias, relu
        const int row0 = tile * MTILE2 + w * 16 + g2;
        const int row1 = row0 + 8;
        float i0 = 0.f, i1 = 0.f;
        if (row0 < N_OUT_C) {
            float dn = g_den[row0];
            i0 = __fdividef(1.f, dn > 0.f ? dn : 1.f);
        }
        if (row1 < N_OUT_C) {
            float dn = g_den[row1];
            i1 = __fdividef(1.f, dn > 0.f ? dn : 1.f);
        }
        #pragma unroll
        for (int nb = 0; nb < 4; nb++) {
            const int c0 = nb * 8 + 2 * t2;
            const float2 bb = *reinterpret_cast<const float2*>(bias + c0);
            if (row0 < N_OUT_C) {
                float2 v;
                v.x = fmaxf(acc[nb][0] * i0 + bb.x, 0.f);
                v.y = fmaxf(acc[nb][1] * i0 + bb.y, 0.f);
                *reinterpret_cast<float2*>(out + (size_t)row0 * COUT + c0) = v;
            }
            if (row1 < N_OUT_C) {
                float2 v;
                v.x = fmaxf(acc[nb][2] * i1 + bb.x, 0.f);
                v.y = fmaxf(acc[nb][3] * i1 + bb.y, 0.f);
                *reinterpret_cast<float2*>(out + (size_t)row1 * COUT + c0) = v;
            }
        }
    }
}

// ================= host =================
extern "C" void kernel_launch(void* const* d_in, const int* in_sizes, int n_in,
                              void* d_out, int out_size)
{
    const float* feats        = (const float*)d_in[0];
    const float* inp_points   = (const float*)d_in[1];
    const float* out_points   = (const float*)d_in[2];
    const float* out_extents  = (const float*)d_in[3];
    const float* scale_compat = (const float*)d_in[4];
    const int*   nidx         = (const int*)  d_in[5];
    // d_in[6] = neighbors_row_splits: fixed degree, unused
    const float* ndist        = (const float*)d_in[7];
    const float* kernW        = (const float*)d_in[8];
    const float* bias         = (const float*)d_in[9];
    float* out = (float*)d_out;

    cudaFuncSetAttribute(k12_fused, cudaFuncAttributeMaxDynamicSharedMemorySize,
                         (int)sizeof(Smem1));

    k0_wfrag<<<32, 256>>>(kernW);
    k12_fused<<<NTILES2, 128, sizeof(Smem1)>>>(feats, inp_points, out_points,
                                               out_extents, scale_compat, nidx,
                                               ndist, bias, out);
}

// round 12
// speedup vs baseline: 1.2007x; 1.2007x over previous
#include <cuda_runtime.h>
#include <cuda_fp16.h>
#include <cstdint>

#define N_OUT_C 50000
#define KNN 32
#define CIN 16
#define COUT 32
#define KC 1024
#define MTILE2 64
#define NTILES2 784             // 784*64 = 50176 >= 50000
#define NGROUPS1 6250           // 50000/8

// ============== device scratch (static, zero-init, no allocations) ==========
__device__ __half g_B16[(size_t)50176 * KC];      // 102.8 MB row-major fp16
__device__ uint4  g_Wfrag[64 * 4 * 32];           // [k16][nb][lane] = b0h,b1h,b0l,b1l
__device__ float  g_den[N_OUT_C];

__device__ __forceinline__ uint32_t smem_u32(const void* p) {
    uint32_t a;
    asm("{ .reg .u64 t; cvta.to.shared.u64 t, %1; cvt.u32.u64 %0, t; }"
        : "=r"(a) : "l"(p));
    return a;
}
__device__ __forceinline__ uint32_t packh2(__half a, __half b) {
    __half2 h = __halves2half2(a, b);
    return *reinterpret_cast<uint32_t*>(&h);
}
__device__ __forceinline__ void ldsm_x4(uint32_t* a, uint32_t addr) {
    asm volatile("ldmatrix.sync.aligned.m8n8.x4.shared.b16 {%0,%1,%2,%3}, [%4];"
                 : "=r"(a[0]), "=r"(a[1]), "=r"(a[2]), "=r"(a[3]) : "r"(addr));
}
__device__ __forceinline__ void mma16816(float* d, const uint32_t* a,
                                         uint32_t b0, uint32_t b1) {
    asm volatile("mma.sync.aligned.m16n8k16.row.col.f32.f16.f16.f32 "
                 "{%0,%1,%2,%3}, {%4,%5,%6,%7}, {%8,%9}, {%0,%1,%2,%3};"
                 : "+f"(d[0]), "+f"(d[1]), "+f"(d[2]), "+f"(d[3])
                 : "r"(a[0]), "r"(a[1]), "r"(a[2]), "r"(a[3]), "r"(b0), "r"(b1));
}
__device__ __forceinline__ void cp16(uint32_t dst, const void* src) {
    asm volatile("cp.async.ca.shared.global [%0], [%1], 16;"
                 :: "r"(dst), "l"(src) : "memory");
}

// ============== K1: wfrag prep (blocks 0-31) + geometry + scatter ===========
#define NW1 4

struct __align__(16) Smem1 {
    float  B[NW1][KC * 2];        // 32768 B, pair-interleaved [kc][2 outs]
    float4 meta4[NW1][2][KNN];    // 4096 B
    int    packs[NW1][2][KNN];    // 1024 B
};                                // 37888 B -> 6 CTAs/SM

__global__ __launch_bounds__(128, 6)
void k1_scatter(const float* __restrict__ feats,
                const float* __restrict__ inp_points,
                const float* __restrict__ out_points,
                const float* __restrict__ out_extents,
                const float* __restrict__ scale_compat,
                const int*   __restrict__ nidx,
                const float* __restrict__ ndist,
                const float* __restrict__ kernW)
{
    extern __shared__ unsigned char raw1[];
    Smem1* S = reinterpret_cast<Smem1*>(raw1);
    const int tid = threadIdx.x, wid = tid >> 5, lane = tid & 31;

    // ---- fold k0: blocks 0-31 pack W into per-lane mma B-fragments ----
    if (blockIdx.x < 32) {
        #pragma unroll
        for (int ii = 0; ii < 2; ii++) {
            int i = blockIdx.x * 256 + ii * 128 + tid;   // 0..8191
            int r = i & 127, nb = r >> 5, ln = r & 31;
            int t = ln & 3, g = ln >> 2, n = nb * 8 + g;
            int kb = (i >> 7) * 16 + 2 * t;
            float w00 = kernW[(kb + 0) * COUT + n];
            float w01 = kernW[(kb + 1) * COUT + n];
            float w10 = kernW[(kb + 8) * COUT + n];
            float w11 = kernW[(kb + 9) * COUT + n];
            __half h00 = __float2half_rn(w00), h01 = __float2half_rn(w01);
            __half h10 = __float2half_rn(w10), h11 = __float2half_rn(w11);
            uint4 v;
            v.x = packh2(h00, h01);
            v.y = packh2(h10, h11);
            v.z = packh2(__float2half_rn(w00 - __half2float(h00)),
                         __float2half_rn(w01 - __half2float(h01)));
            v.w = packh2(__float2half_rn(w10 - __half2float(h10)),
                         __float2half_rn(w11 - __half2float(h11)));
            g_Wfrag[i] = v;
        }
    }

    // ---- software-pipelined edge-input prefetch ----
    int   nbrC[2];
    float distC[2], scC[2];
    {
        const int g0 = blockIdx.x;
        if (g0 < NGROUPS1) {
            #pragma unroll
            for (int s = 0; s < 2; s++) {
                const int eid = (g0 * 8 + wid * 2 + s) * KNN + lane;
                nbrC[s]  = __ldg(&nidx[eid]);
                distC[s] = __ldg(&ndist[eid]);
                scC[s]   = __ldg(&scale_compat[eid]);
            }
        }
    }

    for (int g = blockIdx.x; g < NGROUPS1; g += gridDim.x) {
        const int obase = g * 8 + wid * 2;

        // prefetch next group's edge inputs (hides nidx->points chain)
        int   nbrN[2];
        float distN[2], scN[2];
        const int gn = g + gridDim.x;
        if (gn < NGROUPS1) {
            #pragma unroll
            for (int s = 0; s < 2; s++) {
                const int eid = (gn * 8 + wid * 2 + s) * KNN + lane;
                nbrN[s]  = __ldg(&nidx[eid]);
                distN[s] = __ldg(&ndist[eid]);
                scN[s]   = __ldg(&scale_compat[eid]);
            }
        }

        {   // zero B
            float4* Bz = reinterpret_cast<float4*>(S->B[wid]);
            #pragma unroll
            for (int z = 0; z < 16; z++)
                Bz[z * 32 + lane] = make_float4(0.f, 0.f, 0.f, 0.f);
        }

        #pragma unroll
        for (int s = 0; s < 2; s++) {   // geometry, lane = edge
            const int o = obase + s;
            const int nbr = nbrC[s];
            const float dist = distC[s];
            float tt = 1.f - dist * dist;
            float win = fminf(fmaxf(tt * tt * tt, 0.f), 1.f);
            const float imp = scC[s] * win;

            const float pix = inp_points[nbr * 3 + 0];
            const float piy = inp_points[nbr * 3 + 1];
            const float piz = inp_points[nbr * 3 + 2];
            const float inv = __fdividef(2.f, out_extents[o]);
            const float rx = (pix - out_points[o * 3 + 0]) * inv;
            const float ry = (piy - out_points[o * 3 + 1]) * inv;
            const float rz = (piz - out_points[o * 3 + 2]) * inv;

            const float r = sqrtf(rx * rx + ry * ry + rz * rz);
            const float linf = fmaxf(fabsf(rx), fmaxf(fabsf(ry), fabsf(rz)));
            const float sf = __fdividef(r, fmaxf(linf, 1e-12f));
            float tx = fminf(fmaxf((rx * sf * 0.5f + 0.5f) * 3.f, 0.f), 3.f);
            float ty = fminf(fmaxf((ry * sf * 0.5f + 0.5f) * 3.f, 0.f), 3.f);
            float tz = fminf(fmaxf((rz * sf * 0.5f + 0.5f) * 3.f, 0.f), 3.f);
            float t0x = fminf(floorf(tx), 2.f);
            float t0y = fminf(floorf(ty), 2.f);
            float t0z = fminf(floorf(tz), 2.f);
            int ix = (int)t0x, iy = (int)t0y, iz = (int)t0z;

            S->meta4[wid][s][lane] = make_float4(tx - t0x, ty - t0y, tz - t0z, imp);
            S->packs[wid][s][lane] = nbr | (ix << 20) | (iy << 22) | (iz << 24);

            float dsum = imp;
            #pragma unroll
            for (int off = 16; off; off >>= 1)
                dsum += __shfl_xor_sync(0xffffffffu, dsum, off);
            if (lane == 0) g_den[o] = dsum;
        }
        __syncwarp();

        {   // scatter: half-warp h -> slot h, bank (2c+h)%32 conflict-free
            const int h = lane >> 4, c = lane & 15;
            float* Bw = S->B[wid];
            const float4* m4 = S->meta4[wid][h];
            const int* pk = S->packs[wid][h];
            #pragma unroll 4
            for (int e = 0; e < KNN; e++) {
                const float4 m = m4[e];
                const int p = pk[e];
                const int nb = p & 0xFFFFF;
                const int ix = (p >> 20) & 3, iy = (p >> 22) & 3, iz = (p >> 24) & 3;
                const float fe = __ldg(&feats[nb * CIN + c]) * m.w;
                const float ax1 = fe * m.x, ax0 = fe - ax1;
                const float v01 = ax0 * m.y, v00 = ax0 - v01;
                const float v11 = ax1 * m.y, v10 = ax1 - v11;
                const float wz1 = m.z, wz0 = 1.f - m.z;
                float* Bp = Bw + ((ix * 16 + iy * 4 + iz) * 32 + c * 2 + h);
                Bp[0]   += v00 * wz0;  Bp[32]  += v00 * wz1;
                Bp[128] += v01 * wz0;  Bp[160] += v01 * wz1;
                Bp[512] += v10 * wz0;  Bp[544] += v10 * wz1;
                Bp[640] += v11 * wz0;  Bp[672] += v11 * wz1;
            }
        }
        __syncwarp();

        {   // writeout: row-major fp16, coalesced
            __half2* d0 = reinterpret_cast<__half2*>(g_B16 + (size_t)obase * KC);
            __half2* d1 = reinterpret_cast<__half2*>(g_B16 + (size_t)(obase + 1) * KC);
            const float4* Bq = reinterpret_cast<const float4*>(S->B[wid]);
            #pragma unroll 4
            for (int kt = 0; kt < 16; kt++) {
                float4 v = Bq[kt * 32 + lane];  // (kc,h0)(kc,h1)(kc+1,h0)(kc+1,h1)
                d0[kt * 32 + lane] = __floats2half2_rn(v.x, v.z);
                d1[kt * 32 + lane] = __floats2half2_rn(v.y, v.w);
            }
        }
        __syncwarp();

        #pragma unroll
        for (int s = 0; s < 2; s++) {
            nbrC[s] = nbrN[s]; distC[s] = distN[s]; scC[s] = scN[s];
        }
    }
}

// ======= K2: warp-private 3-stage pipelined fp16 GEMM, no CTA barriers ======
#define NSTG 3
#define STG_B 2304                         // 16 rows * 144 B
#define K2_SMEM (NW1 * NSTG * STG_B)       // 27648 B

__global__ __launch_bounds__(128, 6)
void k2_gemm(float* __restrict__ out, const float* __restrict__ bias)
{
    extern __shared__ unsigned char raw2[];
    const int tid = threadIdx.x, w = tid >> 5, lane = tid & 31;
    const int g2 = lane >> 2, t2 = lane & 3;
    const int tile = blockIdx.x;
    const uint32_t sW = smem_u32(raw2) + w * (NSTG * STG_B);
    const size_t wbase = ((size_t)tile * MTILE2 + w * 16) * KC;   // halfs

    // warp-private chunk issue: 16 rows x 64 halfs, 4 cp16 per lane
    const int prow = lane >> 3, pj = lane & 7;   // pattern: idx = lane + q*32
    #define ISSUE_CHUNK(c, st)                                              \
        do {                                                                \
            _Pragma("unroll")                                               \
            for (int q = 0; q < 4; q++) {                                   \
                int row = prow + q * 4;                                     \
                cp16(sW + (st) * STG_B + row * 144 + pj * 16,               \
                     g_B16 + wbase + (size_t)row * KC + (c) * 64 + pj * 8); \
            }                                                               \
            asm volatile("cp.async.commit_group;" ::: "memory");            \
        } while (0)

    ISSUE_CHUNK(0, 0);
    ISSUE_CHUNK(1, 1);
    ISSUE_CHUNK(2, 2);

    float acc[4][4];
    #pragma unroll
    for (int nb = 0; nb < 4; nb++)
        #pragma unroll
        for (int i = 0; i < 4; i++) acc[nb][i] = 0.f;

    const uint32_t aOff = (lane & 15) * 144 + (lane >> 4) * 16;

    int st = 0;
    for (int c = 0; c < 16; c++) {
        asm volatile("cp.async.wait_group 2;" ::: "memory");
        __syncwarp();

        const uint32_t aStage = sW + st * STG_B + aOff;
        #pragma unroll
        for (int kbl = 0; kbl < 4; kbl++) {
            uint32_t a[4];
            ldsm_x4(a, aStage + kbl * 32);
            const uint4* wf = g_Wfrag + (c * 4 + kbl) * 128 + lane;
            #pragma unroll
            for (int nb = 0; nb < 4; nb++) {
                const uint4 wv = __ldg(&wf[nb * 32]);
                mma16816(acc[nb], a, wv.x, wv.y);   // hi plane
                mma16816(acc[nb], a, wv.z, wv.w);   // lo plane
            }
        }
        __syncwarp();

        if (c + 3 < 16) {
            ISSUE_CHUNK(c + 3, st);
        } else {
            asm volatile("cp.async.commit_group;" ::: "memory");  // empty group
        }
        st = (st == 2) ? 0 : st + 1;
    }

    // epilogue: normalize, bias, relu
    const int row0 = tile * MTILE2 + w * 16 + g2;
    const int row1 = row0 + 8;
    float i0 = 0.f, i1 = 0.f;
    if (row0 < N_OUT_C) {
        float dn = g_den[row0];
        i0 = __fdividef(1.f, dn > 0.f ? dn : 1.f);
    }
    if (row1 < N_OUT_C) {
        float dn = g_den[row1];
        i1 = __fdividef(1.f, dn > 0.f ? dn : 1.f);
    }
    #pragma unroll
    for (int nb = 0; nb < 4; nb++) {
        const int c0 = nb * 8 + 2 * t2;
        const float2 bb = *reinterpret_cast<const float2*>(bias + c0);
        if (row0 < N_OUT_C) {
            float2 v;
            v.x = fmaxf(acc[nb][0] * i0 + bb.x, 0.f);
            v.y = fmaxf(acc[nb][1] * i0 + bb.y, 0.f);
            *reinterpret_cast<float2*>(out + (size_t)row0 * COUT + c0) = v;
        }
        if (row1 < N_OUT_C) {
            float2 v;
            v.x = fmaxf(acc[nb][2] * i1 + bb.x, 0.f);
            v.y = fmaxf(acc[nb][3] * i1 + bb.y, 0.f);
            *reinterpret_cast<float2*>(out + (size_t)row1 * COUT + c0) = v;
        }
    }
}

// ================= host =================
extern "C" void kernel_launch(void* const* d_in, const int* in_sizes, int n_in,
                              void* d_out, int out_size)
{
    const float* feats        = (const float*)d_in[0];
    const float* inp_points   = (const float*)d_in[1];
    const float* out_points   = (const float*)d_in[2];
    const float* out_extents  = (const float*)d_in[3];
    const float* scale_compat = (const float*)d_in[4];
    const int*   nidx         = (const int*)  d_in[5];
    // d_in[6] = neighbors_row_splits: fixed degree, unused
    const float* ndist        = (const float*)d_in[7];
    const float* kernW        = (const float*)d_in[8];
    const float* bias         = (const float*)d_in[9];
    float* out = (float*)d_out;

    cudaFuncSetAttribute(k1_scatter, cudaFuncAttributeMaxDynamicSharedMemorySize,
                         (int)sizeof(Smem1));
    cudaFuncSetAttribute(k2_gemm, cudaFuncAttributeMaxDynamicSharedMemorySize,
                         K2_SMEM);

    k1_scatter<<<888, 128, sizeof(Smem1)>>>(feats, inp_points, out_points,
                                            out_extents, scale_compat, nidx,
                                            ndist, kernW);
    k2_gemm<<<NTILES2, 128, K2_SMEM>>>(out, bias);
}

// round 13
// speedup vs baseline: 1.6948x; 1.4115x over previous
#include <cuda_runtime.h>
#include <cuda_fp16.h>
#include <cstdint>

#define N_OUT_C 50000
#define KNN 32
#define CIN 16
#define COUT 32
#define KC 1024
#define MTILE2 64
#define NTILES2 784             // 784*64 = 50176 >= 50000
#define NW1 4

// ============== device scratch (static, zero-init, no allocations) ==========
__device__ __half g_B16[(size_t)50176 * KC];      // 102.8 MB row-major fp16
__device__ uint4  g_Wfrag[64 * 4 * 32];           // [k16][nb][lane] = b0h,b1h,b0l,b1l
__device__ float  g_den[N_OUT_C];

__device__ __forceinline__ uint32_t smem_u32(const void* p) {
    uint32_t a;
    asm("{ .reg .u64 t; cvta.to.shared.u64 t, %1; cvt.u32.u64 %0, t; }"
        : "=r"(a) : "l"(p));
    return a;
}
__device__ __forceinline__ uint32_t packh2(__half a, __half b) {
    __half2 h = __halves2half2(a, b);
    return *reinterpret_cast<uint32_t*>(&h);
}
__device__ __forceinline__ void ldsm_x4(uint32_t* a, uint32_t addr) {
    asm volatile("ldmatrix.sync.aligned.m8n8.x4.shared.b16 {%0,%1,%2,%3}, [%4];"
                 : "=r"(a[0]), "=r"(a[1]), "=r"(a[2]), "=r"(a[3]) : "r"(addr));
}
__device__ __forceinline__ void ldsm_x2(uint32_t* a, uint32_t addr) {
    asm volatile("ldmatrix.sync.aligned.m8n8.x2.shared.b16 {%0,%1}, [%2];"
                 : "=r"(a[0]), "=r"(a[1]) : "r"(addr));
}
__device__ __forceinline__ void mma16816(float* d, const uint32_t* a,
                                         uint32_t b0, uint32_t b1) {
    asm volatile("mma.sync.aligned.m16n8k16.row.col.f32.f16.f16.f32 "
                 "{%0,%1,%2,%3}, {%4,%5,%6,%7}, {%8,%9}, {%0,%1,%2,%3};"
                 : "+f"(d[0]), "+f"(d[1]), "+f"(d[2]), "+f"(d[3])
                 : "r"(a[0]), "r"(a[1]), "r"(a[2]), "r"(a[3]), "r"(b0), "r"(b1));
}
__device__ __forceinline__ void cp16(uint32_t dst, const void* src) {
    asm volatile("cp.async.ca.shared.global [%0], [%1], 16;"
                 :: "r"(dst), "l"(src) : "memory");
}
__device__ __forceinline__ void sts16(uint32_t addr, float v) {
    unsigned short h = __half_as_ushort(__float2half_rn(v));
    asm volatile("st.shared.u16 [%0], %1;" :: "r"(addr), "h"(h) : "memory");
}

// ======== K1: geometry + dense-S build + HMMA tap-contraction ========
// Per warp smem: St[64 taps][40 halfs] (5120 B) + Ft[16 ch][40 halfs] (1280 B)
// St stride 80 B: ldmatrix rows -> 8 distinct bank-quads (conflict-free).
#define WARP_SMEM 6400
#define K1_SMEM (NW1 * WARP_SMEM)   // 25600 B -> 6 CTAs/SM

__global__ __launch_bounds__(128, 6)
void k1_scatter(const float* __restrict__ feats,
                const float* __restrict__ inp_points,
                const float* __restrict__ out_points,
                const float* __restrict__ out_extents,
                const float* __restrict__ scale_compat,
                const int*   __restrict__ nidx,
                const float* __restrict__ ndist,
                const float* __restrict__ kernW)
{
    extern __shared__ unsigned char raw1[];
    const int tid = threadIdx.x, wid = tid >> 5, lane = tid & 31;
    const uint32_t sSt = smem_u32(raw1) + wid * WARP_SMEM;   // 64 x 40 halfs
    const uint32_t sFt = sSt + 5120;                          // 16 x 40 halfs
    const int g2 = lane >> 2, t2 = lane & 3;

    // ---- fold k0: blocks 0-31 pack W into per-lane mma B-fragments ----
    if (blockIdx.x < 32) {
        #pragma unroll
        for (int ii = 0; ii < 2; ii++) {
            int i = blockIdx.x * 256 + ii * 128 + tid;   // 0..8191
            int r = i & 127, nb = r >> 5, ln = r & 31;
            int t = ln & 3, g = ln >> 2, n = nb * 8 + g;
            int kb = (i >> 7) * 16 + 2 * t;
            float w00 = kernW[(kb + 0) * COUT + n];
            float w01 = kernW[(kb + 1) * COUT + n];
            float w10 = kernW[(kb + 8) * COUT + n];
            float w11 = kernW[(kb + 9) * COUT + n];
            __half h00 = __float2half_rn(w00), h01 = __float2half_rn(w01);
            __half h10 = __float2half_rn(w10), h11 = __float2half_rn(w11);
            uint4 v;
            v.x = packh2(h00, h01);
            v.y = packh2(h10, h11);
            v.z = packh2(__float2half_rn(w00 - __half2float(h00)),
                         __float2half_rn(w01 - __half2float(h01)));
            v.w = packh2(__float2half_rn(w10 - __half2float(h10)),
                         __float2half_rn(w11 - __half2float(h11)));
            g_Wfrag[i] = v;
        }
    }

    const int step = gridDim.x * 4;
    int o = blockIdx.x * 4 + wid;

    int nbrC = 0; float distC = 0.f, scC = 0.f;
    if (o < N_OUT_C) {
        const int eid = o * KNN + lane;
        nbrC  = __ldg(&nidx[eid]);
        distC = __ldg(&ndist[eid]);
        scC   = __ldg(&scale_compat[eid]);
    }

    for (; o < N_OUT_C; o += step) {
        // prefetch next iteration's edge inputs
        int nbrN = 0; float distN = 0.f, scN = 0.f;
        const int on = o + step;
        if (on < N_OUT_C) {
            const int eid = on * KNN + lane;
            nbrN  = __ldg(&nidx[eid]);
            distN = __ldg(&ndist[eid]);
            scN   = __ldg(&scale_compat[eid]);
        }

        // ---- geometry (lane = edge) ----
        float tt = 1.f - distC * distC;
        float win = fminf(fmaxf(tt * tt * tt, 0.f), 1.f);
        const float imp = scC * win;

        const float pix = inp_points[nbrC * 3 + 0];
        const float piy = inp_points[nbrC * 3 + 1];
        const float piz = inp_points[nbrC * 3 + 2];
        const float inv = __fdividef(2.f, out_extents[o]);
        const float rx = (pix - out_points[o * 3 + 0]) * inv;
        const float ry = (piy - out_points[o * 3 + 1]) * inv;
        const float rz = (piz - out_points[o * 3 + 2]) * inv;

        const float r = sqrtf(rx * rx + ry * ry + rz * rz);
        const float linf = fmaxf(fabsf(rx), fmaxf(fabsf(ry), fabsf(rz)));
        const float sf = __fdividef(r, fmaxf(linf, 1e-12f));
        float tx = fminf(fmaxf((rx * sf * 0.5f + 0.5f) * 3.f, 0.f), 3.f);
        float ty = fminf(fmaxf((ry * sf * 0.5f + 0.5f) * 3.f, 0.f), 3.f);
        float tz = fminf(fmaxf((rz * sf * 0.5f + 0.5f) * 3.f, 0.f), 3.f);
        float t0x = fminf(floorf(tx), 2.f);
        float t0y = fminf(floorf(ty), 2.f);
        float t0z = fminf(floorf(tz), 2.f);
        const int ix = (int)t0x, iy = (int)t0y, iz = (int)t0z;
        const float fx = tx - t0x, fy = ty - t0y, fz = tz - t0z;

        // ---- zero St (5120 B) ----
        #pragma unroll
        for (int z = 0; z < 10; z++)
            asm volatile("st.shared.v4.b32 [%0], {%1,%1,%1,%1};"
                         :: "r"(sSt + (z * 32 + lane) * 16), "r"(0u) : "memory");
        __syncwarp();

        // ---- scatter: 8 trilinear weights into St[tap][lane] ----
        {
            const float wx1 = fx, wx0 = 1.f - fx;
            const float wy1 = fy, wy0 = 1.f - fy;
            const float wz1 = fz, wz0 = 1.f - fz;
            const float w00 = wx0 * wy0, w01 = wx0 * wy1;
            const float w10 = wx1 * wy0, w11 = wx1 * wy1;
            const uint32_t base = sSt + (uint32_t)(ix * 16 + iy * 4 + iz) * 80
                                      + lane * 2;
            sts16(base + 0 * 80,  w00 * wz0);
            sts16(base + 1 * 80,  w00 * wz1);
            sts16(base + 4 * 80,  w01 * wz0);
            sts16(base + 5 * 80,  w01 * wz1);
            sts16(base + 16 * 80, w10 * wz0);
            sts16(base + 17 * 80, w10 * wz1);
            sts16(base + 20 * 80, w11 * wz0);
            sts16(base + 21 * 80, w11 * wz1);
        }

        // ---- Ft[ch][edge] = imp * feats[nbr][ch], column store (lane = edge) --
        {
            const float4* fr = reinterpret_cast<const float4*>(
                                   feats + (size_t)nbrC * CIN);
            const float4 f0 = __ldg(fr + 0), f1 = __ldg(fr + 1);
            const float4 f2 = __ldg(fr + 2), f3 = __ldg(fr + 3);
            const uint32_t fb = sFt + lane * 2;
            sts16(fb + 0 * 80,  f0.x * imp);  sts16(fb + 1 * 80,  f0.y * imp);
            sts16(fb + 2 * 80,  f0.z * imp);  sts16(fb + 3 * 80,  f0.w * imp);
            sts16(fb + 4 * 80,  f1.x * imp);  sts16(fb + 5 * 80,  f1.y * imp);
            sts16(fb + 6 * 80,  f1.z * imp);  sts16(fb + 7 * 80,  f1.w * imp);
            sts16(fb + 8 * 80,  f2.x * imp);  sts16(fb + 9 * 80,  f2.y * imp);
            sts16(fb + 10 * 80, f2.z * imp);  sts16(fb + 11 * 80, f2.w * imp);
            sts16(fb + 12 * 80, f3.x * imp);  sts16(fb + 13 * 80, f3.y * imp);
            sts16(fb + 14 * 80, f3.z * imp);  sts16(fb + 15 * 80, f3.w * imp);
        }

        // ---- den = sum of importances ----
        float dsum = imp;
        #pragma unroll
        for (int off = 16; off; off >>= 1)
            dsum += __shfl_xor_sync(0xffffffffu, dsum, off);
        if (lane == 0) g_den[o] = dsum;
        __syncwarp();

        // ---- B(64x16) = St(64x32) @ F(32x16) via 16 HMMA ----
        float acc[4][2][4];
        #pragma unroll
        for (int mt = 0; mt < 4; mt++)
            #pragma unroll
            for (int nt = 0; nt < 2; nt++)
                #pragma unroll
                for (int i = 0; i < 4; i++) acc[mt][nt][i] = 0.f;

        #pragma unroll
        for (int kt = 0; kt < 2; kt++) {
            uint32_t b0[2], b1[2];
            // B-fragment: non-trans ldsm on Ft rows = channels (n), cols = k
            ldsm_x2(b0, sFt + (0 * 8 + (lane & 7)) * 80 + kt * 32
                        + ((lane >> 3) & 1) * 16);
            ldsm_x2(b1, sFt + (1 * 8 + (lane & 7)) * 80 + kt * 32
                        + ((lane >> 3) & 1) * 16);
            #pragma unroll
            for (int mt = 0; mt < 4; mt++) {
                uint32_t a[4];
                ldsm_x4(a, sSt + (mt * 16 + (lane & 15)) * 80 + kt * 32
                           + (lane >> 4) * 16);
                mma16816(acc[mt][0], a, b0[0], b0[1]);
                mma16816(acc[mt][1], a, b1[0], b1[1]);
            }
        }

        // ---- writeout fragments -> g_B16[o][tap*16 + ch] ----
        {
            __half* dst = g_B16 + (size_t)o * KC;
            #pragma unroll
            for (int mt = 0; mt < 4; mt++)
                #pragma unroll
                for (int nt = 0; nt < 2; nt++) {
                    const int off = (mt * 16 + g2) * 16 + nt * 8 + 2 * t2;
                    *reinterpret_cast<__half2*>(dst + off) =
                        __floats2half2_rn(acc[mt][nt][0], acc[mt][nt][1]);
                    *reinterpret_cast<__half2*>(dst + off + 128) =
                        __floats2half2_rn(acc[mt][nt][2], acc[mt][nt][3]);
                }
        }

        nbrC = nbrN; distC = distN; scC = scN;
    }
}

// ======= K2: warp-private 3-stage pipelined fp16 GEMM (unchanged, 36us) =====
#define NSTG 3
#define STG_B 2304                         // 16 rows * 144 B
#define K2_SMEM (NW1 * NSTG * STG_B)       // 27648 B

__global__ __launch_bounds__(128, 6)
void k2_gemm(float* __restrict__ out, const float* __restrict__ bias)
{
    extern __shared__ unsigned char raw2[];
    const int tid = threadIdx.x, w = tid >> 5, lane = tid & 31;
    const int g2 = lane >> 2, t2 = lane & 3;
    const int tile = blockIdx.x;
    const uint32_t sW = smem_u32(raw2) + w * (NSTG * STG_B);
    const size_t wbase = ((size_t)tile * MTILE2 + w * 16) * KC;   // halfs

    const int prow = lane >> 3, pj = lane & 7;
    #define ISSUE_CHUNK(c, st)                                              \
        do {                                                                \
            _Pragma("unroll")                                               \
            for (int q = 0; q < 4; q++) {                                   \
                int row = prow + q * 4;                                     \
                cp16(sW + (st) * STG_B + row * 144 + pj * 16,               \
                     g_B16 + wbase + (size_t)row * KC + (c) * 64 + pj * 8); \
            }                                                               \
            asm volatile("cp.async.commit_group;" ::: "memory");            \
        } while (0)

    ISSUE_CHUNK(0, 0);
    ISSUE_CHUNK(1, 1);
    ISSUE_CHUNK(2, 2);

    float acc[4][4];
    #pragma unroll
    for (int nb = 0; nb < 4; nb++)
        #pragma unroll
        for (int i = 0; i < 4; i++) acc[nb][i] = 0.f;

    const uint32_t aOff = (lane & 15) * 144 + (lane >> 4) * 16;

    int st = 0;
    for (int c = 0; c < 16; c++) {
        asm volatile("cp.async.wait_group 2;" ::: "memory");
        __syncwarp();

        const uint32_t aStage = sW + st * STG_B + aOff;
        #pragma unroll
        for (int kbl = 0; kbl < 4; kbl++) {
            uint32_t a[4];
            ldsm_x4(a, aStage + kbl * 32);
            const uint4* wf = g_Wfrag + (c * 4 + kbl) * 128 + lane;
            #pragma unroll
            for (int nb = 0; nb < 4; nb++) {
                const uint4 wv = __ldg(&wf[nb * 32]);
                mma16816(acc[nb], a, wv.x, wv.y);   // hi plane
                mma16816(acc[nb], a, wv.z, wv.w);   // lo plane
            }
        }
        __syncwarp();

        if (c + 3 < 16) {
            ISSUE_CHUNK(c + 3, st);
        } else {
            asm volatile("cp.async.commit_group;" ::: "memory");  // empty group
        }
        st = (st == 2) ? 0 : st + 1;
    }

    const int row0 = tile * MTILE2 + w * 16 + g2;
    const int row1 = row0 + 8;
    float i0 = 0.f, i1 = 0.f;
    if (row0 < N_OUT_C) {
        float dn = g_den[row0];
        i0 = __fdividef(1.f, dn > 0.f ? dn : 1.f);
    }
    if (row1 < N_OUT_C) {
        float dn = g_den[row1];
        i1 = __fdividef(1.f, dn > 0.f ? dn : 1.f);
    }
    #pragma unroll
    for (int nb = 0; nb < 4; nb++) {
        const int c0 = nb * 8 + 2 * t2;
        const float2 bb = *reinterpret_cast<const float2*>(bias + c0);
        if (row0 < N_OUT_C) {
            float2 v;
            v.x = fmaxf(acc[nb][0] * i0 + bb.x, 0.f);
            v.y = fmaxf(acc[nb][1] * i0 + bb.y, 0.f);
            *reinterpret_cast<float2*>(out + (size_t)row0 * COUT + c0) = v;
        }
        if (row1 < N_OUT_C) {
            float2 v;
            v.x = fmaxf(acc[nb][2] * i1 + bb.x, 0.f);
            v.y = fmaxf(acc[nb][3] * i1 + bb.y, 0.f);
            *reinterpret_cast<float2*>(out + (size_t)row1 * COUT + c0) = v;
        }
    }
}

// ================= host =================
extern "C" void kernel_launch(void* const* d_in, const int* in_sizes, int n_in,
                              void* d_out, int out_size)
{
    const float* feats        = (const float*)d_in[0];
    const float* inp_points   = (const float*)d_in[1];
    const float* out_points   = (const float*)d_in[2];
    const float* out_extents  = (const float*)d_in[3];
    const float* scale_compat = (const float*)d_in[4];
    const int*   nidx         = (const int*)  d_in[5];
    // d_in[6] = neighbors_row_splits: fixed degree, unused
    const float* ndist        = (const float*)d_in[7];
    const float* kernW        = (const float*)d_in[8];
    const float* bias         = (const float*)d_in[9];
    float* out = (float*)d_out;

    cudaFuncSetAttribute(k1_scatter, cudaFuncAttributeMaxDynamicSharedMemorySize,
                         K1_SMEM);
    cudaFuncSetAttribute(k2_gemm, cudaFuncAttributeMaxDynamicSharedMemorySize,
                         K2_SMEM);

    k1_scatter<<<888, 128, K1_SMEM>>>(feats, inp_points, out_points,
                                      out_extents, scale_compat, nidx,
                                      ndist, kernW);
    k2_gemm<<<NTILES2, 128, K2_SMEM>>>(out, bias);
}

// round 14
// speedup vs baseline: 1.7548x; 1.0354x over previous
#include <cuda_runtime.h>
#include <cuda_fp16.h>
#include <cstdint>

#define N_OUT_C 50000
#define KNN 32
#define CIN 16
#define COUT 32
#define KC 1024
#define MTILE2 64
#define NTILES2 784             // 784*64 = 50176 >= 50000
#define NW1 4

// ============== device scratch (static, zero-init, no allocations) ==========
__device__ __half g_B16[(size_t)50176 * KC];      // 102.8 MB, PERMUTED columns
__device__ uint4  g_Wfrag[64 * 4 * 32];           // [k16][nb][lane], permuted rows
__device__ float  g_den[N_OUT_C];

// column permutation: position j in B row -> original kc = tap*16+ch
// j = q*128 + lane*4 + p*2 + e,  q=mt*2+nt
__device__ __forceinline__ int kperm(int j) {
    int q = j >> 7, r = j & 127;
    int ln = r >> 2, p = (r >> 1) & 1, e = r & 1;
    int mt = q >> 1, nt = q & 1;
    int tap = mt * 16 + (ln >> 2) + p * 8;
    int ch  = nt * 8 + 2 * (ln & 3) + e;
    return tap * 16 + ch;
}

__device__ __forceinline__ uint32_t smem_u32(const void* p) {
    uint32_t a;
    asm("{ .reg .u64 t; cvta.to.shared.u64 t, %1; cvt.u32.u64 %0, t; }"
        : "=r"(a) : "l"(p));
    return a;
}
__device__ __forceinline__ uint32_t packh2(__half a, __half b) {
    __half2 h = __halves2half2(a, b);
    return *reinterpret_cast<uint32_t*>(&h);
}
__device__ __forceinline__ void ldsm_x4(uint32_t* a, uint32_t addr) {
    asm volatile("ldmatrix.sync.aligned.m8n8.x4.shared.b16 {%0,%1,%2,%3}, [%4];"
                 : "=r"(a[0]), "=r"(a[1]), "=r"(a[2]), "=r"(a[3]) : "r"(addr));
}
__device__ __forceinline__ void ldsm_x2(uint32_t* a, uint32_t addr) {
    asm volatile("ldmatrix.sync.aligned.m8n8.x2.shared.b16 {%0,%1}, [%2];"
                 : "=r"(a[0]), "=r"(a[1]) : "r"(addr));
}
__device__ __forceinline__ void mma16816(float* d, const uint32_t* a,
                                         uint32_t b0, uint32_t b1) {
    asm volatile("mma.sync.aligned.m16n8k16.row.col.f32.f16.f16.f32 "
                 "{%0,%1,%2,%3}, {%4,%5,%6,%7}, {%8,%9}, {%0,%1,%2,%3};"
                 : "+f"(d[0]), "+f"(d[1]), "+f"(d[2]), "+f"(d[3])
                 : "r"(a[0]), "r"(a[1]), "r"(a[2]), "r"(a[3]), "r"(b0), "r"(b1));
}
__device__ __forceinline__ void cp16(uint32_t dst, const void* src) {
    asm volatile("cp.async.ca.shared.global [%0], [%1], 16;"
                 :: "r"(dst), "l"(src) : "memory");
}
__device__ __forceinline__ void sts16(uint32_t addr, float v) {
    unsigned short h = __half_as_ushort(__float2half_rn(v));
    asm volatile("st.shared.u16 [%0], %1;" :: "r"(addr), "h"(h) : "memory");
}

// ======== K1: geometry + dense-S build + HMMA tap-contraction ========
#define WARP_SMEM 6400
#define K1_SMEM (NW1 * WARP_SMEM)   // 25600 B -> 6 CTAs/SM

__global__ __launch_bounds__(128, 6)
void k1_scatter(const float* __restrict__ feats,
                const float* __restrict__ inp_points,
                const float* __restrict__ out_points,
                const float* __restrict__ out_extents,
                const float* __restrict__ scale_compat,
                const int*   __restrict__ nidx,
                const float* __restrict__ ndist,
                const float* __restrict__ kernW)
{
    extern __shared__ unsigned char raw1[];
    const int tid = threadIdx.x, wid = tid >> 5, lane = tid & 31;
    const uint32_t sSt = smem_u32(raw1) + wid * WARP_SMEM;   // 64 x 40 halfs
    const uint32_t sFt = sSt + 5120;                          // 16 x 40 halfs

    // ---- fold k0: blocks 0-31 pack W (permuted rows) into mma B-fragments ----
    if (blockIdx.x < 32) {
        #pragma unroll
        for (int ii = 0; ii < 2; ii++) {
            int i = blockIdx.x * 256 + ii * 128 + tid;   // 0..8191
            int r = i & 127, nb = r >> 5, ln = r & 31;
            int t = ln & 3, g = ln >> 2, n = nb * 8 + g;
            int j0 = (i >> 7) * 16 + 2 * t;
            float w00 = kernW[kperm(j0 + 0) * COUT + n];
            float w01 = kernW[kperm(j0 + 1) * COUT + n];
            float w10 = kernW[kperm(j0 + 8) * COUT + n];
            float w11 = kernW[kperm(j0 + 9) * COUT + n];
            __half h00 = __float2half_rn(w00), h01 = __float2half_rn(w01);
            __half h10 = __float2half_rn(w10), h11 = __float2half_rn(w11);
            uint4 v;
            v.x = packh2(h00, h01);
            v.y = packh2(h10, h11);
            v.z = packh2(__float2half_rn(w00 - __half2float(h00)),
                         __float2half_rn(w01 - __half2float(h01)));
            v.w = packh2(__float2half_rn(w10 - __half2float(h10)),
                         __float2half_rn(w11 - __half2float(h11)));
            g_Wfrag[i] = v;
        }
    }

    const int step = gridDim.x * 4;
    int o = blockIdx.x * 4 + wid;

    int nbrC = 0; float distC = 0.f, scC = 0.f;
    if (o < N_OUT_C) {
        const int eid = o * KNN + lane;
        nbrC  = __ldg(&nidx[eid]);
        distC = __ldg(&ndist[eid]);
        scC   = __ldg(&scale_compat[eid]);
    }

    for (; o < N_OUT_C; o += step) {
        int nbrN = 0; float distN = 0.f, scN = 0.f;
        const int on = o + step;
        if (on < N_OUT_C) {
            const int eid = on * KNN + lane;
            nbrN  = __ldg(&nidx[eid]);
            distN = __ldg(&ndist[eid]);
            scN   = __ldg(&scale_compat[eid]);
        }

        // ---- geometry (lane = edge) ----
        float tt = 1.f - distC * distC;
        float win = fminf(fmaxf(tt * tt * tt, 0.f), 1.f);
        const float imp = scC * win;

        const float pix = inp_points[nbrC * 3 + 0];
        const float piy = inp_points[nbrC * 3 + 1];
        const float piz = inp_points[nbrC * 3 + 2];
        const float inv = __fdividef(2.f, out_extents[o]);
        const float rx = (pix - out_points[o * 3 + 0]) * inv;
        const float ry = (piy - out_points[o * 3 + 1]) * inv;
        const float rz = (piz - out_points[o * 3 + 2]) * inv;

        const float r = sqrtf(rx * rx + ry * ry + rz * rz);
        const float linf = fmaxf(fabsf(rx), fmaxf(fabsf(ry), fabsf(rz)));
        const float sf = __fdividef(r, fmaxf(linf, 1e-12f));
        float tx = fminf(fmaxf((rx * sf * 0.5f + 0.5f) * 3.f, 0.f), 3.f);
        float ty = fminf(fmaxf((ry * sf * 0.5f + 0.5f) * 3.f, 0.f), 3.f);
        float tz = fminf(fmaxf((rz * sf * 0.5f + 0.5f) * 3.f, 0.f), 3.f);
        float t0x = fminf(floorf(tx), 2.f);
        float t0y = fminf(floorf(ty), 2.f);
        float t0z = fminf(floorf(tz), 2.f);
        const int ix = (int)t0x, iy = (int)t0y, iz = (int)t0z;
        const float fx = tx - t0x, fy = ty - t0y, fz = tz - t0z;

        // ---- zero St (5120 B) ----
        #pragma unroll
        for (int z = 0; z < 10; z++)
            asm volatile("st.shared.v4.b32 [%0], {%1,%1,%1,%1};"
                         :: "r"(sSt + (z * 32 + lane) * 16), "r"(0u) : "memory");
        __syncwarp();

        // ---- scatter: 8 trilinear weights into St[tap][lane] ----
        {
            const float wx1 = fx, wx0 = 1.f - fx;
            const float wy1 = fy, wy0 = 1.f - fy;
            const float wz1 = fz, wz0 = 1.f - fz;
            const float w00 = wx0 * wy0, w01 = wx0 * wy1;
            const float w10 = wx1 * wy0, w11 = wx1 * wy1;
            const uint32_t base = sSt + (uint32_t)(ix * 16 + iy * 4 + iz) * 80
                                      + lane * 2;
            sts16(base + 0 * 80,  w00 * wz0);
            sts16(base + 1 * 80,  w00 * wz1);
            sts16(base + 4 * 80,  w01 * wz0);
            sts16(base + 5 * 80,  w01 * wz1);
            sts16(base + 16 * 80, w10 * wz0);
            sts16(base + 17 * 80, w10 * wz1);
            sts16(base + 20 * 80, w11 * wz0);
            sts16(base + 21 * 80, w11 * wz1);
        }

        // ---- Ft[ch][edge] = imp * feats[nbr][ch] ----
        {
            const float4* fr = reinterpret_cast<const float4*>(
                                   feats + (size_t)nbrC * CIN);
            const float4 f0 = __ldg(fr + 0), f1 = __ldg(fr + 1);
            const float4 f2 = __ldg(fr + 2), f3 = __ldg(fr + 3);
            const uint32_t fb = sFt + lane * 2;
            sts16(fb + 0 * 80,  f0.x * imp);  sts16(fb + 1 * 80,  f0.y * imp);
            sts16(fb + 2 * 80,  f0.z * imp);  sts16(fb + 3 * 80,  f0.w * imp);
            sts16(fb + 4 * 80,  f1.x * imp);  sts16(fb + 5 * 80,  f1.y * imp);
            sts16(fb + 6 * 80,  f1.z * imp);  sts16(fb + 7 * 80,  f1.w * imp);
            sts16(fb + 8 * 80,  f2.x * imp);  sts16(fb + 9 * 80,  f2.y * imp);
            sts16(fb + 10 * 80, f2.z * imp);  sts16(fb + 11 * 80, f2.w * imp);
            sts16(fb + 12 * 80, f3.x * imp);  sts16(fb + 13 * 80, f3.y * imp);
            sts16(fb + 14 * 80, f3.z * imp);  sts16(fb + 15 * 80, f3.w * imp);
        }

        // ---- den = sum of importances ----
        float dsum = imp;
        #pragma unroll
        for (int off = 16; off; off >>= 1)
            dsum += __shfl_xor_sync(0xffffffffu, dsum, off);
        if (lane == 0) g_den[o] = dsum;
        __syncwarp();

        // ---- B(64x16) = St(64x32) @ F(32x16) via 16 HMMA ----
        float acc[4][2][4];
        #pragma unroll
        for (int mt = 0; mt < 4; mt++)
            #pragma unroll
            for (int nt = 0; nt < 2; nt++)
                #pragma unroll
                for (int i = 0; i < 4; i++) acc[mt][nt][i] = 0.f;

        #pragma unroll
        for (int kt = 0; kt < 2; kt++) {
            uint32_t b0[2], b1[2];
            ldsm_x2(b0, sFt + (0 * 8 + (lane & 7)) * 80 + kt * 32
                        + ((lane >> 3) & 1) * 16);
            ldsm_x2(b1, sFt + (1 * 8 + (lane & 7)) * 80 + kt * 32
                        + ((lane >> 3) & 1) * 16);
            #pragma unroll
            for (int mt = 0; mt < 4; mt++) {
                uint32_t a[4];
                ldsm_x4(a, sSt + (mt * 16 + (lane & 15)) * 80 + kt * 32
                           + (lane >> 4) * 16);
                mma16816(acc[mt][0], a, b0[0], b0[1]);
                mma16816(acc[mt][1], a, b1[0], b1[1]);
            }
        }

        // ---- writeout: permuted layout, 8x fully-coalesced STG.64 ----
        {
            __half* dst = g_B16 + (size_t)o * KC;
            #pragma unroll
            for (int mt = 0; mt < 4; mt++)
                #pragma unroll
                for (int nt = 0; nt < 2; nt++) {
                    const int q = mt * 2 + nt;
                    uint2 v;
                    v.x = packh2(__float2half_rn(acc[mt][nt][0]),
                                 __float2half_rn(acc[mt][nt][1]));
                    v.y = packh2(__float2half_rn(acc[mt][nt][2]),
                                 __float2half_rn(acc[mt][nt][3]));
                    *reinterpret_cast<uint2*>(dst + q * 128 + lane * 4) = v;
                }
        }

        nbrC = nbrN; distC = distN; scC = scN;
    }
}

// ======= K2: warp-private 3-stage pipelined fp16 GEMM (unchanged) ======
#define NSTG 3
#define STG_B 2304                         // 16 rows * 144 B
#define K2_SMEM (NW1 * NSTG * STG_B)       // 27648 B

__global__ __launch_bounds__(128, 6)
void k2_gemm(float* __restrict__ out, const float* __restrict__ bias)
{
    extern __shared__ unsigned char raw2[];
    const int tid = threadIdx.x, w = tid >> 5, lane = tid & 31;
    const int g2 = lane >> 2, t2 = lane & 3;
    const int tile = blockIdx.x;
    const uint32_t sW = smem_u32(raw2) + w * (NSTG * STG_B);
    const size_t wbase = ((size_t)tile * MTILE2 + w * 16) * KC;   // halfs

    const int prow = lane >> 3, pj = lane & 7;
    #define ISSUE_CHUNK(c, st)                                              \
        do {                                                                \
            _Pragma("unroll")                                               \
            for (int q = 0; q < 4; q++) {                                   \
                int row = prow + q * 4;                                     \
                cp16(sW + (st) * STG_B + row * 144 + pj * 16,               \
                     g_B16 + wbase + (size_t)row * KC + (c) * 64 + pj * 8); \
            }                                                               \
            asm volatile("cp.async.commit_group;" ::: "memory");            \
        } while (0)

    ISSUE_CHUNK(0, 0);
    ISSUE_CHUNK(1, 1);
    ISSUE_CHUNK(2, 2);

    float acc[4][4];
    #pragma unroll
    for (int nb = 0; nb < 4; nb++)
        #pragma unroll
        for (int i = 0; i < 4; i++) acc[nb][i] = 0.f;

    const uint32_t aOff = (lane & 15) * 144 + (lane >> 4) * 16;

    int st = 0;
    for (int c = 0; c < 16; c++) {
        asm volatile("cp.async.wait_group 2;" ::: "memory");
        __syncwarp();

        const uint32_t aStage = sW + st * STG_B + aOff;
        #pragma unroll
        for (int kbl = 0; kbl < 4; kbl++) {
            uint32_t a[4];
            ldsm_x4(a, aStage + kbl * 32);
            const uint4* wf = g_Wfrag + (c * 4 + kbl) * 128 + lane;
            #pragma unroll
            for (int nb = 0; nb < 4; nb++) {
                const uint4 wv = __ldg(&wf[nb * 32]);
                mma16816(acc[nb], a, wv.x, wv.y);   // hi plane
                mma16816(acc[nb], a, wv.z, wv.w);   // lo plane
            }
        }
        __syncwarp();

        if (c + 3 < 16) {
            ISSUE_CHUNK(c + 3, st);
        } else {
            asm volatile("cp.async.commit_group;" ::: "memory");  // empty group
        }
        st = (st == 2) ? 0 : st + 1;
    }

    const int row0 = tile * MTILE2 + w * 16 + g2;
    const int row1 = row0 + 8;
    float i0 = 0.f, i1 = 0.f;
    if (row0 < N_OUT_C) {
        float dn = g_den[row0];
        i0 = __fdividef(1.f, dn > 0.f ? dn : 1.f);
    }
    if (row1 < N_OUT_C) {
        float dn = g_den[row1];
        i1 = __fdividef(1.f, dn > 0.f ? dn : 1.f);
    }
    #pragma unroll
    for (int nb = 0; nb < 4; nb++) {
        const int c0 = nb * 8 + 2 * t2;
        const float2 bb = *reinterpret_cast<const float2*>(bias + c0);
        if (row0 < N_OUT_C) {
            float2 v;
            v.x = fmaxf(acc[nb][0] * i0 + bb.x, 0.f);
            v.y = fmaxf(acc[nb][1] * i0 + bb.y, 0.f);
            *reinterpret_cast<float2*>(out + (size_t)row0 * COUT + c0) = v;
        }
        if (row1 < N_OUT_C) {
            float2 v;
            v.x = fmaxf(acc[nb][2] * i1 + bb.x, 0.f);
            v.y = fmaxf(acc[nb][3] * i1 + bb.y, 0.f);
            *reinterpret_cast<float2*>(out + (size_t)row1 * COUT + c0) = v;
        }
    }
}

// ================= host =================
extern "C" void kernel_launch(void* const* d_in, const int* in_sizes, int n_in,
                              void* d_out, int out_size)
{
    const float* feats        = (const float*)d_in[0];
    const float* inp_points   = (const float*)d_in[1];
    const float* out_points   = (const float*)d_in[2];
    const float* out_extents  = (const float*)d_in[3];
    const float* scale_compat = (const float*)d_in[4];
    const int*   nidx         = (const int*)  d_in[5];
    // d_in[6] = neighbors_row_splits: fixed degree, unused
    const float* ndist        = (const float*)d_in[7];
    const float* kernW        = (const float*)d_in[8];
    const float* bias         = (const float*)d_in[9];
    float* out = (float*)d_out;

    cudaFuncSetAttribute(k1_scatter, cudaFuncAttributeMaxDynamicSharedMemorySize,
                         K1_SMEM);
    cudaFuncSetAttribute(k2_gemm, cudaFuncAttributeMaxDynamicSharedMemorySize,
                         K2_SMEM);

    k1_scatter<<<888, 128, K1_SMEM>>>(feats, inp_points, out_points,
                                      out_extents, scale_compat, nidx,
                                      ndist, kernW);
    k2_gemm<<<NTILES2, 128, K2_SMEM>>>(out, bias);
}

// round 15
// speedup vs baseline: 1.9431x; 1.1073x over previous
#include <cuda_runtime.h>
#include <cuda_fp16.h>
#include <cstdint>

#define N_OUT_C 50000
#define KNN 32
#define CIN 16
#define COUT 32
#define KC 1024
#define MTILE2 64
#define NTILES2 784             // 784*64 = 50176 >= 50000
#define NW1 4
#define FULLM 0xffffffffu

// ============== device scratch (static, zero-init, no allocations) ==========
__device__ __half g_B16[(size_t)50176 * KC];      // 102.8 MB, PERMUTED columns
__device__ uint4  g_Wfrag[64 * 4 * 32];           // [k16][nb][lane], permuted rows
__device__ float  g_den[N_OUT_C];

// column permutation: position j in B row -> original kc = tap*16+ch
__device__ __forceinline__ int kperm(int j) {
    int q = j >> 7, r = j & 127;
    int ln = r >> 2, p = (r >> 1) & 1, e = r & 1;
    int mt = q >> 1, nt = q & 1;
    int tap = mt * 16 + (ln >> 2) + p * 8;
    int ch  = nt * 8 + 2 * (ln & 3) + e;
    return tap * 16 + ch;
}

__device__ __forceinline__ uint32_t smem_u32(const void* p) {
    uint32_t a;
    asm("{ .reg .u64 t; cvta.to.shared.u64 t, %1; cvt.u32.u64 %0, t; }"
        : "=r"(a) : "l"(p));
    return a;
}
__device__ __forceinline__ uint32_t packh2(__half a, __half b) {
    __half2 h = __halves2half2(a, b);
    return *reinterpret_cast<uint32_t*>(&h);
}
__device__ __forceinline__ void ldsm_x4(uint32_t* a, uint32_t addr) {
    asm volatile("ldmatrix.sync.aligned.m8n8.x4.shared.b16 {%0,%1,%2,%3}, [%4];"
                 : "=r"(a[0]), "=r"(a[1]), "=r"(a[2]), "=r"(a[3]) : "r"(addr));
}
__device__ __forceinline__ void ldsm_x2t(uint32_t* a, uint32_t addr) {
    asm volatile("ldmatrix.sync.aligned.m8n8.x2.trans.shared.b16 {%0,%1}, [%2];"
                 : "=r"(a[0]), "=r"(a[1]) : "r"(addr));
}
__device__ __forceinline__ void mma16816(float* d, const uint32_t* a,
                                         uint32_t b0, uint32_t b1) {
    asm volatile("mma.sync.aligned.m16n8k16.row.col.f32.f16.f16.f32 "
                 "{%0,%1,%2,%3}, {%4,%5,%6,%7}, {%8,%9}, {%0,%1,%2,%3};"
                 : "+f"(d[0]), "+f"(d[1]), "+f"(d[2]), "+f"(d[3])
                 : "r"(a[0]), "r"(a[1]), "r"(a[2]), "r"(a[3]), "r"(b0), "r"(b1));
}
__device__ __forceinline__ void cp16(uint32_t dst, const void* src) {
    asm volatile("cp.async.ca.shared.global [%0], [%1], 16;"
                 :: "r"(dst), "l"(src) : "memory");
}
__device__ __forceinline__ void sts16(uint32_t addr, float v) {
    unsigned short h = __half_as_ushort(__float2half_rn(v));
    asm volatile("st.shared.u16 [%0], %1;" :: "r"(addr), "h"(h) : "memory");
}

// ======== K1: geometry + dense-S build + HMMA tap-contraction ========
// Per warp smem: St[64 taps][40 halfs] (5120 B) + Ft[32 edges][48 B] (1536 B)
#define WARP_SMEM 6656
#define K1_SMEM (NW1 * WARP_SMEM)   // 26624 B -> 6 CTAs/SM

__global__ __launch_bounds__(128, 6)
void k1_scatter(const float* __restrict__ feats,
                const float* __restrict__ inp_points,
                const float* __restrict__ out_points,
                const float* __restrict__ out_extents,
                const float* __restrict__ scale_compat,
                const int*   __restrict__ nidx,
                const float* __restrict__ ndist,
                const float* __restrict__ kernW)
{
    extern __shared__ unsigned char raw1[];
    const int tid = threadIdx.x, wid = tid >> 5, lane = tid & 31;
    const uint32_t sSt = smem_u32(raw1) + wid * WARP_SMEM;   // 64 x 40 halfs
    const uint32_t sFt = sSt + 5120;                          // 32 x 48 B

    // ---- fold k0: blocks 0-31 pack W (permuted rows) into mma B-fragments ----
    if (blockIdx.x < 32) {
        #pragma unroll
        for (int ii = 0; ii < 2; ii++) {
            int i = blockIdx.x * 256 + ii * 128 + tid;   // 0..8191
            int r = i & 127, nb = r >> 5, ln = r & 31;
            int t = ln & 3, g = ln >> 2, n = nb * 8 + g;
            int j0 = (i >> 7) * 16 + 2 * t;
            float w00 = kernW[kperm(j0 + 0) * COUT + n];
            float w01 = kernW[kperm(j0 + 1) * COUT + n];
            float w10 = kernW[kperm(j0 + 8) * COUT + n];
            float w11 = kernW[kperm(j0 + 9) * COUT + n];
            __half h00 = __float2half_rn(w00), h01 = __float2half_rn(w01);
            __half h10 = __float2half_rn(w10), h11 = __float2half_rn(w11);
            uint4 v;
            v.x = packh2(h00, h01);
            v.y = packh2(h10, h11);
            v.z = packh2(__float2half_rn(w00 - __half2float(h00)),
                         __float2half_rn(w01 - __half2float(h01)));
            v.w = packh2(__float2half_rn(w10 - __half2float(h10)),
                         __float2half_rn(w11 - __half2float(h11)));
            g_Wfrag[i] = v;
        }
    }

    const int step = gridDim.x * 4;
    int o = blockIdx.x * 4 + wid;

    int nbrC = 0; float distC = 0.f, scC = 0.f;
    if (o < N_OUT_C) {
        const int eid = o * KNN + lane;
        nbrC  = __ldg(&nidx[eid]);
        distC = __ldg(&ndist[eid]);
        scC   = __ldg(&scale_compat[eid]);
    }

    for (; o < N_OUT_C; o += step) {
        int nbrN = 0; float distN = 0.f, scN = 0.f;
        const int on = o + step;
        if (on < N_OUT_C) {
            const int eid = on * KNN + lane;
            nbrN  = __ldg(&nidx[eid]);
            distN = __ldg(&ndist[eid]);
            scN   = __ldg(&scale_compat[eid]);
        }

        // ---- cooperative point gather: 8 nbrs x 3 words per pass ----
        float pv[4];
        {
            const int c3 = lane & 3;
            #pragma unroll
            for (int p = 0; p < 4; p++) {
                const int e8 = p * 8 + (lane >> 2);
                const int nbp = __shfl_sync(FULLM, nbrC, e8);
                pv[p] = (c3 < 3)
                      ? __ldg(inp_points + (size_t)nbp * 3 + c3) : 0.f;
            }
        }
        // route coords back to edge-lanes
        float pix, piy, piz;
        {
            const int src = (lane & 7) * 4;
            const int ps = lane >> 3;
            float a0 = __shfl_sync(FULLM, pv[0], src);
            float a1 = __shfl_sync(FULLM, pv[1], src);
            float a2 = __shfl_sync(FULLM, pv[2], src);
            float a3 = __shfl_sync(FULLM, pv[3], src);
            pix = ps == 0 ? a0 : ps == 1 ? a1 : ps == 2 ? a2 : a3;
            a0 = __shfl_sync(FULLM, pv[0], src + 1);
            a1 = __shfl_sync(FULLM, pv[1], src + 1);
            a2 = __shfl_sync(FULLM, pv[2], src + 1);
            a3 = __shfl_sync(FULLM, pv[3], src + 1);
            piy = ps == 0 ? a0 : ps == 1 ? a1 : ps == 2 ? a2 : a3;
            a0 = __shfl_sync(FULLM, pv[0], src + 2);
            a1 = __shfl_sync(FULLM, pv[1], src + 2);
            a2 = __shfl_sync(FULLM, pv[2], src + 2);
            a3 = __shfl_sync(FULLM, pv[3], src + 2);
            piz = ps == 0 ? a0 : ps == 1 ? a1 : ps == 2 ? a2 : a3;
        }

        // ---- geometry (lane = edge) ----
        float tt = 1.f - distC * distC;
        float win = fminf(fmaxf(tt * tt * tt, 0.f), 1.f);
        const float imp = scC * win;

        const float inv = __fdividef(2.f, out_extents[o]);
        const float rx = (pix - out_points[o * 3 + 0]) * inv;
        const float ry = (piy - out_points[o * 3 + 1]) * inv;
        const float rz = (piz - out_points[o * 3 + 2]) * inv;

        const float r = sqrtf(rx * rx + ry * ry + rz * rz);
        const float linf = fmaxf(fabsf(rx), fmaxf(fabsf(ry), fabsf(rz)));
        const float sf = __fdividef(r, fmaxf(linf, 1e-12f));
        float tx = fminf(fmaxf((rx * sf * 0.5f + 0.5f) * 3.f, 0.f), 3.f);
        float ty = fminf(fmaxf((ry * sf * 0.5f + 0.5f) * 3.f, 0.f), 3.f);
        float tz = fminf(fmaxf((rz * sf * 0.5f + 0.5f) * 3.f, 0.f), 3.f);
        float t0x = fminf(floorf(tx), 2.f);
        float t0y = fminf(floorf(ty), 2.f);
        float t0z = fminf(floorf(tz), 2.f);
        const int ix = (int)t0x, iy = (int)t0y, iz = (int)t0z;
        const float fx = tx - t0x, fy = ty - t0y, fz = tz - t0z;

        // ---- zero St (5120 B) ----
        #pragma unroll
        for (int z = 0; z < 10; z++)
            asm volatile("st.shared.v4.b32 [%0], {%1,%1,%1,%1};"
                         :: "r"(sSt + (z * 32 + lane) * 16), "r"(0u) : "memory");
        __syncwarp();

        // ---- scatter: 8 trilinear weights into St[tap][lane] ----
        {
            const float wx1 = fx, wx0 = 1.f - fx;
            const float wy1 = fy, wy0 = 1.f - fy;
            const float wz1 = fz, wz0 = 1.f - fz;
            const float w00 = wx0 * wy0, w01 = wx0 * wy1;
            const float w10 = wx1 * wy0, w11 = wx1 * wy1;
            const uint32_t base = sSt + (uint32_t)(ix * 16 + iy * 4 + iz) * 80
                                      + lane * 2;
            sts16(base + 0 * 80,  w00 * wz0);
            sts16(base + 1 * 80,  w00 * wz1);
            sts16(base + 4 * 80,  w01 * wz0);
            sts16(base + 5 * 80,  w01 * wz1);
            sts16(base + 16 * 80, w10 * wz0);
            sts16(base + 17 * 80, w10 * wz1);
            sts16(base + 20 * 80, w11 * wz0);
            sts16(base + 21 * 80, w11 * wz1);
        }

        // ---- den = sum of importances ----
        float dsum = imp;
        #pragma unroll
        for (int off = 16; off; off >>= 1)
            dsum += __shfl_xor_sync(FULLM, dsum, off);
        if (lane == 0) g_den[o] = dsum;

        // ---- cooperative feats gather: Ft[e][48B] = imp_e * feats[nbr_e] ----
        {
            const int c3 = lane & 3;
            #pragma unroll
            for (int p = 0; p < 4; p++) {
                const int e8 = p * 8 + (lane >> 2);
                const int nbp  = __shfl_sync(FULLM, nbrC, e8);
                const float ie = __shfl_sync(FULLM, imp, e8);
                const float4 f = __ldg(reinterpret_cast<const float4*>(
                                       feats + (size_t)nbp * CIN) + c3);
                uint2 v;
                v.x = packh2(__float2half_rn(f.x * ie),
                             __float2half_rn(f.y * ie));
                v.y = packh2(__float2half_rn(f.z * ie),
                             __float2half_rn(f.w * ie));
                asm volatile("st.shared.v2.b32 [%0], {%1, %2};"
                             :: "r"(sFt + e8 * 48 + c3 * 8),
                                "r"(v.x), "r"(v.y) : "memory");
            }
        }
        __syncwarp();

        // ---- B(64x16) = St(64x32) @ F(32x16) via 16 HMMA ----
        float acc[4][2][4];
        #pragma unroll
        for (int mt = 0; mt < 4; mt++)
            #pragma unroll
            for (int nt = 0; nt < 2; nt++)
                #pragma unroll
                for (int i = 0; i < 4; i++) acc[mt][nt][i] = 0.f;

        #pragma unroll
        for (int kt = 0; kt < 2; kt++) {
            uint32_t b0[2], b1[2];
            // B fragment via canonical ldmatrix.trans on k-major Ft rows
            const uint32_t fb = sFt + (kt * 16 + (lane & 15)) * 48;
            ldsm_x2t(b0, fb);        // channels 0-7
            ldsm_x2t(b1, fb + 16);   // channels 8-15
            #pragma unroll
            for (int mt = 0; mt < 4; mt++) {
                uint32_t a[4];
                ldsm_x4(a, sSt + (mt * 16 + (lane & 15)) * 80 + kt * 32
                           + (lane >> 4) * 16);
                mma16816(acc[mt][0], a, b0[0], b0[1]);
                mma16816(acc[mt][1], a, b1[0], b1[1]);
            }
        }

        // ---- writeout: permuted layout, 8x fully-coalesced STG.64 ----
        {
            __half* dst = g_B16 + (size_t)o * KC;
            #pragma unroll
            for (int mt = 0; mt < 4; mt++)
                #pragma unroll
                for (int nt = 0; nt < 2; nt++) {
                    const int q = mt * 2 + nt;
                    uint2 v;
                    v.x = packh2(__float2half_rn(acc[mt][nt][0]),
                                 __float2half_rn(acc[mt][nt][1]));
                    v.y = packh2(__float2half_rn(acc[mt][nt][2]),
                                 __float2half_rn(acc[mt][nt][3]));
                    *reinterpret_cast<uint2*>(dst + q * 128 + lane * 4) = v;
                }
        }

        nbrC = nbrN; distC = distN; scC = scN;
    }
}

// ======= K2: warp-private 3-stage pipelined fp16 GEMM (unchanged) ======
#define NSTG 3
#define STG_B 2304                         // 16 rows * 144 B
#define K2_SMEM (NW1 * NSTG * STG_B)       // 27648 B

__global__ __launch_bounds__(128, 6)
void k2_gemm(float* __restrict__ out, const float* __restrict__ bias)
{
    extern __shared__ unsigned char raw2[];
    const int tid = threadIdx.x, w = tid >> 5, lane = tid & 31;
    const int g2 = lane >> 2, t2 = lane & 3;
    const int tile = blockIdx.x;
    const uint32_t sW = smem_u32(raw2) + w * (NSTG * STG_B);
    const size_t wbase = ((size_t)tile * MTILE2 + w * 16) * KC;   // halfs

    const int prow = lane >> 3, pj = lane & 7;
    #define ISSUE_CHUNK(c, st)                                              \
        do {                                                                \
            _Pragma("unroll")                                               \
            for (int q = 0; q < 4; q++) {                                   \
                int row = prow + q * 4;                                     \
                cp16(sW + (st) * STG_B + row * 144 + pj * 16,               \
                     g_B16 + wbase + (size_t)row * KC + (c) * 64 + pj * 8); \
            }                                                               \
            asm volatile("cp.async.commit_group;" ::: "memory");            \
        } while (0)

    ISSUE_CHUNK(0, 0);
    ISSUE_CHUNK(1, 1);
    ISSUE_CHUNK(2, 2);

    float acc[4][4];
    #pragma unroll
    for (int nb = 0; nb < 4; nb++)
        #pragma unroll
        for (int i = 0; i < 4; i++) acc[nb][i] = 0.f;

    const uint32_t aOff = (lane & 15) * 144 + (lane >> 4) * 16;

    int st = 0;
    for (int c = 0; c < 16; c++) {
        asm volatile("cp.async.wait_group 2;" ::: "memory");
        __syncwarp();

        const uint32_t aStage = sW + st * STG_B + aOff;
        #pragma unroll
        for (int kbl = 0; kbl < 4; kbl++) {
            uint32_t a[4];
            ldsm_x4(a, aStage + kbl * 32);
            const uint4* wf = g_Wfrag + (c * 4 + kbl) * 128 + lane;
            #pragma unroll
            for (int nb = 0; nb < 4; nb++) {
                const uint4 wv = __ldg(&wf[nb * 32]);
                mma16816(acc[nb], a, wv.x, wv.y);   // hi plane
                mma16816(acc[nb], a, wv.z, wv.w);   // lo plane
            }
        }
        __syncwarp();

        if (c + 3 < 16) {
            ISSUE_CHUNK(c + 3, st);
        } else {
            asm volatile("cp.async.commit_group;" ::: "memory");  // empty group
        }
        st = (st == 2) ? 0 : st + 1;
    }

    const int row0 = tile * MTILE2 + w * 16 + g2;
    const int row1 = row0 + 8;
    float i0 = 0.f, i1 = 0.f;
    if (row0 < N_OUT_C) {
        float dn = g_den[row0];
        i0 = __fdividef(1.f, dn > 0.f ? dn : 1.f);
    }
    if (row1 < N_OUT_C) {
        float dn = g_den[row1];
        i1 = __fdividef(1.f, dn > 0.f ? dn : 1.f);
    }
    #pragma unroll
    for (int nb = 0; nb < 4; nb++) {
        const int c0 = nb * 8 + 2 * t2;
        const float2 bb = *reinterpret_cast<const float2*>(bias + c0);
        if (row0 < N_OUT_C) {
            float2 v;
            v.x = fmaxf(acc[nb][0] * i0 + bb.x, 0.f);
            v.y = fmaxf(acc[nb][1] * i0 + bb.y, 0.f);
            *reinterpret_cast<float2*>(out + (size_t)row0 * COUT + c0) = v;
        }
        if (row1 < N_OUT_C) {
            float2 v;
            v.x = fmaxf(acc[nb][2] * i1 + bb.x, 0.f);
            v.y = fmaxf(acc[nb][3] * i1 + bb.y, 0.f);
            *reinterpret_cast<float2*>(out + (size_t)row1 * COUT + c0) = v;
        }
    }
}

// ================= host =================
extern "C" void kernel_launch(void* const* d_in, const int* in_sizes, int n_in,
                              void* d_out, int out_size)
{
    const float* feats        = (const float*)d_in[0];
    const float* inp_points   = (const float*)d_in[1];
    const float* out_points   = (const float*)d_in[2];
    const float* out_extents  = (const float*)d_in[3];
    const float* scale_compat = (const float*)d_in[4];
    const int*   nidx         = (const int*)  d_in[5];
    // d_in[6] = neighbors_row_splits: fixed degree, unused
    const float* ndist        = (const float*)d_in[7];
    const float* kernW        = (const float*)d_in[8];
    const float* bias         = (const float*)d_in[9];
    float* out = (float*)d_out;

    cudaFuncSetAttribute(k1_scatter, cudaFuncAttributeMaxDynamicSharedMemorySize,
                         K1_SMEM);
    cudaFuncSetAttribute(k2_gemm, cudaFuncAttributeMaxDynamicSharedMemorySize,
                         K2_SMEM);

    k1_scatter<<<888, 128, K1_SMEM>>>(feats, inp_points, out_points,
                                      out_extents, scale_compat, nidx,
                                      ndist, kernW);
    k2_gemm<<<NTILES2, 128, K2_SMEM>>>(out, bias);
}